// round 8
// baseline (speedup 1.0000x reference)
#include <cuda_runtime.h>
#include <math.h>

#define HW   (128*128)
#define VOL  (128*128*128)
#define NF   12582912
#define NV   4194304

// Accumulators: [0]=reg SSD, [1..3]=pair0 (gp,gg,pp), [4..6]=pair1, [7,8]=tv0(prod,add), [9,10]=tv1
// Zero-initialized at module load; finalizing block re-zeroes after each use.
__device__ double g_acc[16];
__device__ unsigned g_done;   // completion counter, reset by finalizer

// 16-byte cp.async with zero-fill for out-of-bounds (src-size = 0)
__device__ __forceinline__ void cpa16(void* s, const void* g, bool ok) {
    unsigned sa = (unsigned)__cvta_generic_to_shared(s);
    int sz = ok ? 16 : 0;
    asm volatile("cp.async.cg.shared.global [%0], [%1], 16, %2;\n"
                 :: "r"(sa), "l"(g), "r"(sz) : "memory");
}
__device__ __forceinline__ void cpa_commit() {
    asm volatile("cp.async.commit_group;\n" ::: "memory");
}
__device__ __forceinline__ void cpa_wait1() {
    asm volatile("cp.async.wait_group 1;\n" ::: "memory");
}

#define N_LCC 512
#define N_REG 768
#define N_TV  1024    // 512 per pair
#define GRID  (N_LCC + N_REG + N_TV)

struct __align__(16) SmemLcc {
    float raw[2][2][20][72];   // [buf][vol][row][col]; col 0 = global w0-4
    float xs[2][20][64];       // x-passed 5-sums
    float sh[3][16];
};

// Load one z-plane (both vols, 20 rows x 72 cols) via 16B cp.async.
// Window covers global w0-4 .. w0+67; fully-OOB/pad 4-float groups zero-fill.
__device__ __forceinline__ void load_plane(
    float (*rawbuf)[20][72], const float* __restrict__ gt,
    const float* __restrict__ pr, int z, int h0, int w0, int tid)
{
    bool zv = ((unsigned)z < 128u);
#pragma unroll
    for (int k = 0; k < 2; ++k) {
        int idx = tid + k * 512;
        if (idx < 720) {                       // 2 vols * 20 rows * 18 groups
            int v   = (idx >= 360);
            int rem = idx - (v ? 360 : 0);
            int rr  = rem / 18;
            int g4  = rem - rr * 18;
            int h   = h0 - 2 + rr;
            int gw  = w0 - 4 + g4 * 4;
            bool ok = zv && ((unsigned)h < 128u) && ((unsigned)gw < 128u);
            const float* g = (v ? pr : gt) + (ok ? (z * HW + h * 128 + gw) : 0);
            cpa16(&rawbuf[v][rr][g4 * 4], g, ok);
        }
    }
}

__device__ void do_lcc(SmemLcc* S, int b,
    const float* __restrict__ I0, const float* __restrict__ I0R,
    const float* __restrict__ I1, const float* __restrict__ I1R)
{
    int zs   = b & 7;
    int wt   = (b >> 3) & 1;
    int ht   = (b >> 4) & 7;
    int n    = (b >> 7) & 1;
    int pair = (b >> 8) & 1;

    const float* gt = (pair ? I1  : I0)  + n * VOL;
    const float* pr = (pair ? I1R : I0R) + n * VOL;

    int h0 = ht << 4;
    int w0 = wt << 6;
    int d0 = zs << 4;   // 16-plane z segment

    int tid  = threadIdx.x;
    int wloc = tid & 63;
    int r0   = tid >> 6;         // owns output rows 2r0 and 2r0+1

    float m[2][2][5];            // [rowpair][vol][zwin] xy-sums
    float rc[2][2][3];           // raw-center delay line
#pragma unroll
    for (int c = 0; c < 2; ++c)
#pragma unroll
        for (int v = 0; v < 2; ++v) {
#pragma unroll
            for (int k = 0; k < 5; ++k) m[c][v][k] = 0.f;
#pragma unroll
            for (int k = 0; k < 3; ++k) rc[c][v][k] = 0.f;
        }

    float sgp = 0.f, sgg = 0.f, spp = 0.f;

    load_plane(S->raw[(d0 - 2) & 1], gt, pr, d0 - 2, h0, w0, tid);
    cpa_commit();

    int zlast = d0 + 17;
    for (int z = d0 - 2; z <= zlast; ++z) {
        int buf = z & 1;
        if (z < zlast)
            load_plane(S->raw[(z + 1) & 1], gt, pr, z + 1, h0, w0, tid);
        cpa_commit();
        cpa_wait1();
        __syncthreads();

        // raw-center delay push
#pragma unroll
        for (int c = 0; c < 2; ++c) {
#pragma unroll
            for (int v = 0; v < 2; ++v) {
                rc[c][v][2] = rc[c][v][1];
                rc[c][v][1] = rc[c][v][0];
                rc[c][v][0] = S->raw[buf][v][2 * r0 + c + 2][wloc + 4];
            }
        }

        // x-pass: 320 tasks; each produces 8 adjacent sums from 4 LDS.128
        if (tid < 320) {
            int v   = (tid >= 160);
            int rem = tid - (v ? 160 : 0);
            int rr  = rem >> 3;
            int g   = rem & 7;                 // 8 outputs starting at 8g
            const float4* r4 = (const float4*)S->raw[buf][v][rr];
            float4 A = r4[2 * g], B = r4[2 * g + 1], C = r4[2 * g + 2], D = r4[2 * g + 3];
            float f2 = A.z, f3 = A.w, f4 = B.x, f5 = B.y, f6 = B.z, f7 = B.w;
            float f8 = C.x, f9 = C.y, f10 = C.z, f11 = C.w, f12 = D.x, f13 = D.y;
            float o0 = f2 + f3 + f4 + f5 + f6;
            float o1 = o0 - f2 + f7;
            float o2 = o1 - f3 + f8;
            float o3 = o2 - f4 + f9;
            float o4 = o3 - f5 + f10;
            float o5 = o4 - f6 + f11;
            float o6 = o5 - f7 + f12;
            float o7 = o6 - f8 + f13;
            float4* x4 = (float4*)S->xs[v][rr];
            x4[2 * g]     = make_float4(o0, o1, o2, o3);
            x4[2 * g + 1] = make_float4(o4, o5, o6, o7);
        }
        __syncthreads();

        // y-pass: rows 2r0, 2r0+1 share xs rows 2r0..2r0+5
#pragma unroll
        for (int v = 0; v < 2; ++v) {
            int rl = 2 * r0;
            float y0 = S->xs[v][rl][wloc];
            float y1 = S->xs[v][rl + 1][wloc];
            float y2 = S->xs[v][rl + 2][wloc];
            float y3 = S->xs[v][rl + 3][wloc];
            float y4 = S->xs[v][rl + 4][wloc];
            float y5 = S->xs[v][rl + 5][wloc];
            float mv0 = y0 + y1 + y2 + y3 + y4;
            float mv1 = mv0 - y0 + y5;
            m[0][v][0] = m[0][v][1]; m[0][v][1] = m[0][v][2];
            m[0][v][2] = m[0][v][3]; m[0][v][3] = m[0][v][4]; m[0][v][4] = mv0;
            m[1][v][0] = m[1][v][1]; m[1][v][1] = m[1][v][2];
            m[1][v][2] = m[1][v][3]; m[1][v][3] = m[1][v][4]; m[1][v][4] = mv1;
        }

        if (z >= d0 + 2) {
#pragma unroll
            for (int c = 0; c < 2; ++c) {
                float mg = (m[c][0][0] + m[c][0][1] + m[c][0][2] + m[c][0][3] + m[c][0][4]) * 0.008f;
                float mp = (m[c][1][0] + m[c][1][1] + m[c][1][2] + m[c][1][3] + m[c][1][4]) * 0.008f;
                float dg = rc[c][0][2] - mg;
                float dp = rc[c][1][2] - mp;
                sgp += dg * dp;
                sgg += dg * dg;
                spp += dp * dp;
            }
        }
    }

    unsigned lane = tid & 31, wd = tid >> 5;
#pragma unroll
    for (int o = 16; o; o >>= 1) {
        sgp += __shfl_down_sync(0xffffffffu, sgp, o);
        sgg += __shfl_down_sync(0xffffffffu, sgg, o);
        spp += __shfl_down_sync(0xffffffffu, spp, o);
    }
    if (lane == 0) { S->sh[0][wd] = sgp; S->sh[1][wd] = sgg; S->sh[2][wd] = spp; }
    __syncthreads();
    if (tid == 0) {
        float a = 0.f, b2 = 0.f, c = 0.f;
#pragma unroll
        for (int i = 0; i < 16; ++i) { a += S->sh[0][i]; b2 += S->sh[1][i]; c += S->sh[2][i]; }
        atomicAdd(&g_acc[1 + 3 * pair], (double)a);
        atomicAdd(&g_acc[2 + 3 * pair], (double)b2);
        atomicAdd(&g_acc[3 + 3 * pair], (double)c);
    }
}

__device__ void do_reg(SmemLcc* S, int b,
    const float4* __restrict__ A, const float4* __restrict__ B)
{
    const int n4 = NF / 4;
    float s = 0.f;
    for (int i = b * 512 + threadIdx.x; i < n4; i += N_REG * 512) {
        float4 a = A[i], bb = B[i];
        float d0 = a.x - bb.x, d1 = a.y - bb.y, d2 = a.z - bb.z, d3 = a.w - bb.w;
        s += d0 * d0 + d1 * d1 + d2 * d2 + d3 * d3;
    }
    int tid = threadIdx.x;
    unsigned lane = tid & 31, wd = tid >> 5;
#pragma unroll
    for (int o = 16; o; o >>= 1) s += __shfl_down_sync(0xffffffffu, s, o);
    if (lane == 0) S->sh[0][wd] = s;
    __syncthreads();
    if (tid == 0) {
        float a = 0.f;
#pragma unroll
        for (int i = 0; i < 16; ++i) a += S->sh[0][i];
        atomicAdd(&g_acc[0], (double)a);
    }
}

__device__ void do_tv(SmemLcc* S, int b,
    const float4* __restrict__ S0, const float4* __restrict__ S0g,
    const float4* __restrict__ S1, const float4* __restrict__ S1g)
{
    const int n4 = NV / 4;
    int p = b >= 512;
    const float4* Sv  = p ? S1  : S0;
    const float4* Sg  = p ? S1g : S0g;
    int bid = b - (p << 9);

    float sp = 0.f, sa = 0.f;
    for (int i = bid * 512 + threadIdx.x; i < n4; i += 512 * 512) {
        float4 a = Sv[i], bb = Sg[i];
        sp += a.x * bb.x + a.y * bb.y + a.z * bb.z + a.w * bb.w;
        sa += a.x + bb.x + a.y + bb.y + a.z + bb.z + a.w + bb.w;
    }
    int tid = threadIdx.x;
    unsigned lane = tid & 31, wd = tid >> 5;
#pragma unroll
    for (int o = 16; o; o >>= 1) {
        sp += __shfl_down_sync(0xffffffffu, sp, o);
        sa += __shfl_down_sync(0xffffffffu, sa, o);
    }
    if (lane == 0) { S->sh[0][wd] = sp; S->sh[1][wd] = sa; }
    __syncthreads();
    if (tid == 0) {
        float a = 0.f, b2 = 0.f;
#pragma unroll
        for (int i = 0; i < 16; ++i) { a += S->sh[0][i]; b2 += S->sh[1][i]; }
        atomicAdd(&g_acc[7 + 2 * p], (double)a);
        atomicAdd(&g_acc[8 + 2 * p], (double)b2);
    }
}

// ---------------------------------------------------------------------------
// Mega kernel: lcc blocks first (latency/smem heavy, low DRAM BW), then reg/tv
// blocks (pure BW) backfill. The last block to finish finalizes the scalar
// (no second kernel launch) and resets the accumulators for the next replay.
// ---------------------------------------------------------------------------
__global__ void __launch_bounds__(512) k_mega(
    const float* __restrict__ F0,  const float* __restrict__ F0g,
    const float* __restrict__ I0,  const float* __restrict__ I0R,
    const float* __restrict__ I1,  const float* __restrict__ I1R,
    const float* __restrict__ S0,  const float* __restrict__ S0g,
    const float* __restrict__ S1,  const float* __restrict__ S1g,
    float* __restrict__ out)
{
    __shared__ SmemLcc S;
    int b = blockIdx.x;
    if (b < N_LCC) {
        do_lcc(&S, b, I0, I0R, I1, I1R);
    } else if (b < N_LCC + N_REG) {
        do_reg(&S, b - N_LCC, (const float4*)F0, (const float4*)F0g);
    } else {
        do_tv(&S, b - N_LCC - N_REG, (const float4*)S0, (const float4*)S0g,
              (const float4*)S1, (const float4*)S1g);
    }

    if (threadIdx.x == 0) {
        __threadfence();                       // release this block's atomics
        unsigned old = atomicAdd(&g_done, 1u);
        if (old == GRID - 1) {                 // all contributions visible (L2)
            volatile double* acc = g_acc;
            double reg = sqrt(acc[0]) / (double)NF;
            double l = 0.0;
            for (int p = 0; p < 2; ++p) {
                double gp = acc[1 + 3 * p], gg = acc[2 + 3 * p], pp = acc[3 + 3 * p];
                double den = gg * pp;
                if (den < 1e-5) den = 1e-5;
                l += -(gp * gp / den) / (double)NV;
            }
            double t = 0.0;
            for (int p = 0; p < 2; ++p) {
                double prod = acc[7 + 2 * p], add = acc[8 + 2 * p];
                double den = add;
                if (den < 1e-5) den = 1e-5;
                t += -prod / den;
            }
            out[0] = (float)(reg + 10.0 * l + 10.0 * t);
            // restore invariant for next replay
            for (int i = 0; i < 16; ++i) acc[i] = 0.0;
            g_done = 0u;
            __threadfence();
        }
    }
}

extern "C" void kernel_launch(void* const* d_in, const int* in_sizes, int n_in,
                              void* d_out, int out_size) {
    const float* F0  = (const float*)d_in[0];
    const float* F0g = (const float*)d_in[1];
    const float* I0  = (const float*)d_in[2];
    const float* I0R = (const float*)d_in[3];
    const float* I1  = (const float*)d_in[4];
    const float* I1R = (const float*)d_in[5];
    const float* S0  = (const float*)d_in[6];
    const float* S0g = (const float*)d_in[7];
    const float* S1  = (const float*)d_in[8];
    const float* S1g = (const float*)d_in[9];

    k_mega<<<GRID, 512>>>(F0, F0g, I0, I0R, I1, I1R, S0, S0g, S1, S1g,
                          (float*)d_out);
}

// round 10
// speedup vs baseline: 1.0176x; 1.0176x over previous
#include <cuda_runtime.h>
#include <math.h>

#define HW   (128*128)
#define VOL  (128*128*128)
#define NF   12582912
#define NV   4194304

// Accumulators: [0]=reg SSD, [1..3]=pair0 (gp,gg,pp), [4..6]=pair1, [7,8]=tv0(prod,add), [9,10]=tv1
// Zero-initialized at module load; k_final re-zeroes after each use.
__device__ double g_acc[16];

// 16-byte cp.async with zero-fill for out-of-bounds (src-size = 0)
__device__ __forceinline__ void cpa16(void* s, const void* g, bool ok) {
    unsigned sa = (unsigned)__cvta_generic_to_shared(s);
    int sz = ok ? 16 : 0;
    asm volatile("cp.async.cg.shared.global [%0], [%1], 16, %2;\n"
                 :: "r"(sa), "l"(g), "r"(sz) : "memory");
}
__device__ __forceinline__ void cpa_commit() {
    asm volatile("cp.async.commit_group;\n" ::: "memory");
}
__device__ __forceinline__ void cpa_wait1() {
    asm volatile("cp.async.wait_group 1;\n" ::: "memory");
}

#define N_LCC 512
#define N_REG 768
#define N_TV  1024    // 512 per pair
#define GRID  (N_LCC + N_REG + N_TV)   // 2304 = 256 groups * 9

struct __align__(16) SmemLcc {
    float raw[2][2][20][72];   // [buf][vol][row][col]; col 0 = global w0-4
    float xs[2][20][64];       // x-passed 5-sums
    float sh[3][16];
};

// Load one z-plane (both vols, 20 rows x 72 cols) via 16B cp.async.
// Window covers global w0-4 .. w0+67; fully-OOB/pad 4-float groups zero-fill.
__device__ __forceinline__ void load_plane(
    float (*rawbuf)[20][72], const float* __restrict__ gt,
    const float* __restrict__ pr, int z, int h0, int w0, int tid)
{
    bool zv = ((unsigned)z < 128u);
#pragma unroll
    for (int k = 0; k < 2; ++k) {
        int idx = tid + k * 512;
        if (idx < 720) {                       // 2 vols * 20 rows * 18 groups
            int v   = (idx >= 360);
            int rem = idx - (v ? 360 : 0);
            int rr  = rem / 18;
            int g4  = rem - rr * 18;
            int h   = h0 - 2 + rr;
            int gw  = w0 - 4 + g4 * 4;
            bool ok = zv && ((unsigned)h < 128u) && ((unsigned)gw < 128u);
            const float* g = (v ? pr : gt) + (ok ? (z * HW + h * 128 + gw) : 0);
            cpa16(&rawbuf[v][rr][g4 * 4], g, ok);
        }
    }
}

__device__ void do_lcc(SmemLcc* S, int b,
    const float* __restrict__ I0, const float* __restrict__ I0R,
    const float* __restrict__ I1, const float* __restrict__ I1R)
{
    int zs   = b & 7;
    int wt   = (b >> 3) & 1;
    int ht   = (b >> 4) & 7;
    int n    = (b >> 7) & 1;
    int pair = (b >> 8) & 1;

    const float* gt = (pair ? I1  : I0)  + n * VOL;
    const float* pr = (pair ? I1R : I0R) + n * VOL;

    int h0 = ht << 4;
    int w0 = wt << 6;
    int d0 = zs << 4;   // 16-plane z segment

    int tid  = threadIdx.x;
    int wloc = tid & 63;
    int r0   = tid >> 6;         // owns output rows 2r0 and 2r0+1

    float m[2][2][5];            // [rowpair][vol][zwin] xy-sums
    float rc[2][2][3];           // raw-center delay line
#pragma unroll
    for (int c = 0; c < 2; ++c)
#pragma unroll
        for (int v = 0; v < 2; ++v) {
#pragma unroll
            for (int k = 0; k < 5; ++k) m[c][v][k] = 0.f;
#pragma unroll
            for (int k = 0; k < 3; ++k) rc[c][v][k] = 0.f;
        }

    float sgp = 0.f, sgg = 0.f, spp = 0.f;

    load_plane(S->raw[(d0 - 2) & 1], gt, pr, d0 - 2, h0, w0, tid);
    cpa_commit();

    int zlast = d0 + 17;
    for (int z = d0 - 2; z <= zlast; ++z) {
        int buf = z & 1;
        if (z < zlast)
            load_plane(S->raw[(z + 1) & 1], gt, pr, z + 1, h0, w0, tid);
        cpa_commit();
        cpa_wait1();
        __syncthreads();

        // raw-center delay push
#pragma unroll
        for (int c = 0; c < 2; ++c) {
#pragma unroll
            for (int v = 0; v < 2; ++v) {
                rc[c][v][2] = rc[c][v][1];
                rc[c][v][1] = rc[c][v][0];
                rc[c][v][0] = S->raw[buf][v][2 * r0 + c + 2][wloc + 4];
            }
        }

        // x-pass: 320 tasks; each produces 8 adjacent sums from 4 LDS.128
        if (tid < 320) {
            int v   = (tid >= 160);
            int rem = tid - (v ? 160 : 0);
            int rr  = rem >> 3;
            int g   = rem & 7;                 // 8 outputs starting at 8g
            const float4* r4 = (const float4*)S->raw[buf][v][rr];
            float4 A = r4[2 * g], B = r4[2 * g + 1], C = r4[2 * g + 2], D = r4[2 * g + 3];
            float f2 = A.z, f3 = A.w, f4 = B.x, f5 = B.y, f6 = B.z, f7 = B.w;
            float f8 = C.x, f9 = C.y, f10 = C.z, f11 = C.w, f12 = D.x, f13 = D.y;
            float o0 = f2 + f3 + f4 + f5 + f6;
            float o1 = o0 - f2 + f7;
            float o2 = o1 - f3 + f8;
            float o3 = o2 - f4 + f9;
            float o4 = o3 - f5 + f10;
            float o5 = o4 - f6 + f11;
            float o6 = o5 - f7 + f12;
            float o7 = o6 - f8 + f13;
            float4* x4 = (float4*)S->xs[v][rr];
            x4[2 * g]     = make_float4(o0, o1, o2, o3);
            x4[2 * g + 1] = make_float4(o4, o5, o6, o7);
        }
        __syncthreads();

        // y-pass: rows 2r0, 2r0+1 share xs rows 2r0..2r0+5
#pragma unroll
        for (int v = 0; v < 2; ++v) {
            int rl = 2 * r0;
            float y0 = S->xs[v][rl][wloc];
            float y1 = S->xs[v][rl + 1][wloc];
            float y2 = S->xs[v][rl + 2][wloc];
            float y3 = S->xs[v][rl + 3][wloc];
            float y4 = S->xs[v][rl + 4][wloc];
            float y5 = S->xs[v][rl + 5][wloc];
            float mv0 = y0 + y1 + y2 + y3 + y4;
            float mv1 = mv0 - y0 + y5;
            m[0][v][0] = m[0][v][1]; m[0][v][1] = m[0][v][2];
            m[0][v][2] = m[0][v][3]; m[0][v][3] = m[0][v][4]; m[0][v][4] = mv0;
            m[1][v][0] = m[1][v][1]; m[1][v][1] = m[1][v][2];
            m[1][v][2] = m[1][v][3]; m[1][v][3] = m[1][v][4]; m[1][v][4] = mv1;
        }

        if (z >= d0 + 2) {
#pragma unroll
            for (int c = 0; c < 2; ++c) {
                float mg = (m[c][0][0] + m[c][0][1] + m[c][0][2] + m[c][0][3] + m[c][0][4]) * 0.008f;
                float mp = (m[c][1][0] + m[c][1][1] + m[c][1][2] + m[c][1][3] + m[c][1][4]) * 0.008f;
                float dg = rc[c][0][2] - mg;
                float dp = rc[c][1][2] - mp;
                sgp += dg * dp;
                sgg += dg * dg;
                spp += dp * dp;
            }
        }
    }

    unsigned lane = tid & 31, wd = tid >> 5;
#pragma unroll
    for (int o = 16; o; o >>= 1) {
        sgp += __shfl_down_sync(0xffffffffu, sgp, o);
        sgg += __shfl_down_sync(0xffffffffu, sgg, o);
        spp += __shfl_down_sync(0xffffffffu, spp, o);
    }
    if (lane == 0) { S->sh[0][wd] = sgp; S->sh[1][wd] = sgg; S->sh[2][wd] = spp; }
    __syncthreads();
    if (tid == 0) {
        float a = 0.f, b2 = 0.f, c = 0.f;
#pragma unroll
        for (int i = 0; i < 16; ++i) { a += S->sh[0][i]; b2 += S->sh[1][i]; c += S->sh[2][i]; }
        atomicAdd(&g_acc[1 + 3 * pair], (double)a);
        atomicAdd(&g_acc[2 + 3 * pair], (double)b2);
        atomicAdd(&g_acc[3 + 3 * pair], (double)c);
    }
}

__device__ void do_reg(SmemLcc* S, int b,
    const float4* __restrict__ A, const float4* __restrict__ B)
{
    const int n4 = NF / 4;
    float s = 0.f;
    for (int i = b * 512 + threadIdx.x; i < n4; i += N_REG * 512) {
        float4 a = A[i], bb = B[i];
        float d0 = a.x - bb.x, d1 = a.y - bb.y, d2 = a.z - bb.z, d3 = a.w - bb.w;
        s += d0 * d0 + d1 * d1 + d2 * d2 + d3 * d3;
    }
    int tid = threadIdx.x;
    unsigned lane = tid & 31, wd = tid >> 5;
#pragma unroll
    for (int o = 16; o; o >>= 1) s += __shfl_down_sync(0xffffffffu, s, o);
    if (lane == 0) S->sh[0][wd] = s;
    __syncthreads();
    if (tid == 0) {
        float a = 0.f;
#pragma unroll
        for (int i = 0; i < 16; ++i) a += S->sh[0][i];
        atomicAdd(&g_acc[0], (double)a);
    }
}

__device__ void do_tv(SmemLcc* S, int b,
    const float4* __restrict__ S0, const float4* __restrict__ S0g,
    const float4* __restrict__ S1, const float4* __restrict__ S1g)
{
    const int n4 = NV / 4;
    int p = b >= 512;
    const float4* Sv  = p ? S1  : S0;
    const float4* Sg  = p ? S1g : S0g;
    int bid = b - (p << 9);

    float sp = 0.f, sa = 0.f;
    for (int i = bid * 512 + threadIdx.x; i < n4; i += 512 * 512) {
        float4 a = Sv[i], bb = Sg[i];
        sp += a.x * bb.x + a.y * bb.y + a.z * bb.z + a.w * bb.w;
        sa += a.x + bb.x + a.y + bb.y + a.z + bb.z + a.w + bb.w;
    }
    int tid = threadIdx.x;
    unsigned lane = tid & 31, wd = tid >> 5;
#pragma unroll
    for (int o = 16; o; o >>= 1) {
        sp += __shfl_down_sync(0xffffffffu, sp, o);
        sa += __shfl_down_sync(0xffffffffu, sa, o);
    }
    if (lane == 0) { S->sh[0][wd] = sp; S->sh[1][wd] = sa; }
    __syncthreads();
    if (tid == 0) {
        float a = 0.f, b2 = 0.f;
#pragma unroll
        for (int i = 0; i < 16; ++i) { a += S->sh[0][i]; b2 += S->sh[1][i]; }
        atomicAdd(&g_acc[7 + 2 * p], (double)a);
        atomicAdd(&g_acc[8 + 2 * p], (double)b2);
    }
}

// ---------------------------------------------------------------------------
// Mega kernel with INTERLEAVED roles: each group of 9 consecutive bids holds
// 2 lcc + 3 reg + 4 tv blocks, so every resident wave mixes LSU-bound lcc
// work with DRAM-bound reductions and both resources stay busy from t=0.
// ---------------------------------------------------------------------------
__global__ void __launch_bounds__(512) k_mega(
    const float* __restrict__ F0,  const float* __restrict__ F0g,
    const float* __restrict__ I0,  const float* __restrict__ I0R,
    const float* __restrict__ I1,  const float* __restrict__ I1R,
    const float* __restrict__ S0,  const float* __restrict__ S0g,
    const float* __restrict__ S1,  const float* __restrict__ S1g)
{
    __shared__ SmemLcc S;
    int b = blockIdx.x;
    int grp  = b / 9;
    int slot = b - grp * 9;
    if (slot < 2) {
        do_lcc(&S, grp * 2 + slot, I0, I0R, I1, I1R);
    } else if (slot < 5) {
        do_reg(&S, grp * 3 + (slot - 2), (const float4*)F0, (const float4*)F0g);
    } else {
        do_tv(&S, grp * 4 + (slot - 5), (const float4*)S0, (const float4*)S0g,
              (const float4*)S1, (const float4*)S1g);
    }
}

// 32-thread finalize: parallel accumulator loads (MLP hides L2 latency).
__global__ void k_final(float* out) {
    __shared__ double a[16];
    int t = threadIdx.x;
    if (t < 16) a[t] = g_acc[t];
    __syncwarp();
    if (t == 0) {
        double reg = sqrt(a[0]) / (double)NF;
        double l = 0.0;
        for (int p = 0; p < 2; ++p) {
            double gp = a[1 + 3 * p], gg = a[2 + 3 * p], pp = a[3 + 3 * p];
            double den = gg * pp;
            if (den < 1e-5) den = 1e-5;
            l += -(gp * gp / den) / (double)NV;
        }
        double tv = 0.0;
        for (int p = 0; p < 2; ++p) {
            double den = a[8 + 2 * p];
            if (den < 1e-5) den = 1e-5;
            tv += -a[7 + 2 * p] / den;
        }
        out[0] = (float)(reg + 10.0 * l + 10.0 * tv);
    }
    __syncwarp();
    if (t < 16) g_acc[t] = 0.0;   // restore invariant for next replay
}

extern "C" void kernel_launch(void* const* d_in, const int* in_sizes, int n_in,
                              void* d_out, int out_size) {
    const float* F0  = (const float*)d_in[0];
    const float* F0g = (const float*)d_in[1];
    const float* I0  = (const float*)d_in[2];
    const float* I0R = (const float*)d_in[3];
    const float* I1  = (const float*)d_in[4];
    const float* I1R = (const float*)d_in[5];
    const float* S0  = (const float*)d_in[6];
    const float* S0g = (const float*)d_in[7];
    const float* S1  = (const float*)d_in[8];
    const float* S1g = (const float*)d_in[9];

    k_mega<<<GRID, 512>>>(F0, F0g, I0, I0R, I1, I1R, S0, S0g, S1, S1g);
    k_final<<<1, 32>>>((float*)d_out);
}

// round 12
// speedup vs baseline: 1.0180x; 1.0004x over previous
#include <cuda_runtime.h>
#include <math.h>

#define HW   (128*128)
#define VOL  (128*128*128)
#define NF   12582912
#define NV   4194304

// Accumulators: [0]=reg SSD, [1..3]=pair0 (gp,gg,pp), [4..6]=pair1, [7,8]=tv0(prod,add), [9,10]=tv1
// Zero-initialized at module load; finalizing block re-zeroes after each use.
__device__ double g_acc[16];
__device__ unsigned g_done;   // completion counter, reset by finalizer

// 16-byte cp.async with zero-fill for out-of-bounds (src-size = 0)
__device__ __forceinline__ void cpa16(void* s, const void* g, bool ok) {
    unsigned sa = (unsigned)__cvta_generic_to_shared(s);
    int sz = ok ? 16 : 0;
    asm volatile("cp.async.cg.shared.global [%0], [%1], 16, %2;\n"
                 :: "r"(sa), "l"(g), "r"(sz) : "memory");
}
__device__ __forceinline__ void cpa_commit() {
    asm volatile("cp.async.commit_group;\n" ::: "memory");
}
__device__ __forceinline__ void cpa_wait1() {
    asm volatile("cp.async.wait_group 1;\n" ::: "memory");
}

#define N_LCC 512
#define N_REG 768
#define N_TV  1024    // 512 per pair
#define GRID  (N_LCC + N_REG + N_TV)

struct __align__(16) SmemLcc {
    float raw[2][2][20][72];   // [buf][vol][row][col]; col 0 = global w0-4
    float xs[2][20][64];       // x-passed 5-sums
    float sh[3][16];
    float facc[16];            // finalize scratch
    unsigned last;             // "this block is the finalizer" flag
};

// Load one z-plane (both vols, 20 rows x 72 cols) via 16B cp.async.
__device__ __forceinline__ void load_plane(
    float (*rawbuf)[20][72], const float* __restrict__ gt,
    const float* __restrict__ pr, int z, int h0, int w0, int tid)
{
    bool zv = ((unsigned)z < 128u);
#pragma unroll
    for (int k = 0; k < 2; ++k) {
        int idx = tid + k * 512;
        if (idx < 720) {                       // 2 vols * 20 rows * 18 groups
            int v   = (idx >= 360);
            int rem = idx - (v ? 360 : 0);
            int rr  = rem / 18;
            int g4  = rem - rr * 18;
            int h   = h0 - 2 + rr;
            int gw  = w0 - 4 + g4 * 4;
            bool ok = zv && ((unsigned)h < 128u) && ((unsigned)gw < 128u);
            const float* g = (v ? pr : gt) + (ok ? (z * HW + h * 128 + gw) : 0);
            cpa16(&rawbuf[v][rr][g4 * 4], g, ok);
        }
    }
}

__device__ void do_lcc(SmemLcc* S, int b,
    const float* __restrict__ I0, const float* __restrict__ I0R,
    const float* __restrict__ I1, const float* __restrict__ I1R)
{
    int zs   = b & 7;
    int wt   = (b >> 3) & 1;
    int ht   = (b >> 4) & 7;
    int n    = (b >> 7) & 1;
    int pair = (b >> 8) & 1;

    const float* gt = (pair ? I1  : I0)  + n * VOL;
    const float* pr = (pair ? I1R : I0R) + n * VOL;

    int h0 = ht << 4;
    int w0 = wt << 6;
    int d0 = zs << 4;   // 16-plane z segment

    int tid  = threadIdx.x;
    int wloc = tid & 63;
    int r0   = tid >> 6;         // owns output rows 2r0 and 2r0+1

    float m[2][2][5];            // [rowpair][vol][zwin] xy-sums
    float rc[2][2][3];           // raw-center delay line
#pragma unroll
    for (int c = 0; c < 2; ++c)
#pragma unroll
        for (int v = 0; v < 2; ++v) {
#pragma unroll
            for (int k = 0; k < 5; ++k) m[c][v][k] = 0.f;
#pragma unroll
            for (int k = 0; k < 3; ++k) rc[c][v][k] = 0.f;
        }

    float sgp = 0.f, sgg = 0.f, spp = 0.f;

    load_plane(S->raw[(d0 - 2) & 1], gt, pr, d0 - 2, h0, w0, tid);
    cpa_commit();

    int zlast = d0 + 17;
    for (int z = d0 - 2; z <= zlast; ++z) {
        int buf = z & 1;
        if (z < zlast)
            load_plane(S->raw[(z + 1) & 1], gt, pr, z + 1, h0, w0, tid);
        cpa_commit();
        cpa_wait1();
        __syncthreads();

        // raw-center delay push
#pragma unroll
        for (int c = 0; c < 2; ++c) {
#pragma unroll
            for (int v = 0; v < 2; ++v) {
                rc[c][v][2] = rc[c][v][1];
                rc[c][v][1] = rc[c][v][0];
                rc[c][v][0] = S->raw[buf][v][2 * r0 + c + 2][wloc + 4];
            }
        }

        // x-pass: 320 tasks; each produces 8 adjacent sums from 4 LDS.128
        if (tid < 320) {
            int v   = (tid >= 160);
            int rem = tid - (v ? 160 : 0);
            int rr  = rem >> 3;
            int g   = rem & 7;                 // 8 outputs starting at 8g
            const float4* r4 = (const float4*)S->raw[buf][v][rr];
            float4 A = r4[2 * g], B = r4[2 * g + 1], C = r4[2 * g + 2], D = r4[2 * g + 3];
            float f2 = A.z, f3 = A.w, f4 = B.x, f5 = B.y, f6 = B.z, f7 = B.w;
            float f8 = C.x, f9 = C.y, f10 = C.z, f11 = C.w, f12 = D.x, f13 = D.y;
            float o0 = f2 + f3 + f4 + f5 + f6;
            float o1 = o0 - f2 + f7;
            float o2 = o1 - f3 + f8;
            float o3 = o2 - f4 + f9;
            float o4 = o3 - f5 + f10;
            float o5 = o4 - f6 + f11;
            float o6 = o5 - f7 + f12;
            float o7 = o6 - f8 + f13;
            float4* x4 = (float4*)S->xs[v][rr];
            x4[2 * g]     = make_float4(o0, o1, o2, o3);
            x4[2 * g + 1] = make_float4(o4, o5, o6, o7);
        }
        __syncthreads();

        // y-pass: rows 2r0, 2r0+1 share xs rows 2r0..2r0+5
#pragma unroll
        for (int v = 0; v < 2; ++v) {
            int rl = 2 * r0;
            float y0 = S->xs[v][rl][wloc];
            float y1 = S->xs[v][rl + 1][wloc];
            float y2 = S->xs[v][rl + 2][wloc];
            float y3 = S->xs[v][rl + 3][wloc];
            float y4 = S->xs[v][rl + 4][wloc];
            float y5 = S->xs[v][rl + 5][wloc];
            float mv0 = y0 + y1 + y2 + y3 + y4;
            float mv1 = mv0 - y0 + y5;
            m[0][v][0] = m[0][v][1]; m[0][v][1] = m[0][v][2];
            m[0][v][2] = m[0][v][3]; m[0][v][3] = m[0][v][4]; m[0][v][4] = mv0;
            m[1][v][0] = m[1][v][1]; m[1][v][1] = m[1][v][2];
            m[1][v][2] = m[1][v][3]; m[1][v][3] = m[1][v][4]; m[1][v][4] = mv1;
        }

        if (z >= d0 + 2) {
#pragma unroll
            for (int c = 0; c < 2; ++c) {
                float mg = (m[c][0][0] + m[c][0][1] + m[c][0][2] + m[c][0][3] + m[c][0][4]) * 0.008f;
                float mp = (m[c][1][0] + m[c][1][1] + m[c][1][2] + m[c][1][3] + m[c][1][4]) * 0.008f;
                float dg = rc[c][0][2] - mg;
                float dp = rc[c][1][2] - mp;
                sgp += dg * dp;
                sgg += dg * dg;
                spp += dp * dp;
            }
        }
    }

    unsigned lane = tid & 31, wd = tid >> 5;
#pragma unroll
    for (int o = 16; o; o >>= 1) {
        sgp += __shfl_down_sync(0xffffffffu, sgp, o);
        sgg += __shfl_down_sync(0xffffffffu, sgg, o);
        spp += __shfl_down_sync(0xffffffffu, spp, o);
    }
    if (lane == 0) { S->sh[0][wd] = sgp; S->sh[1][wd] = sgg; S->sh[2][wd] = spp; }
    __syncthreads();
    if (tid == 0) {
        float a = 0.f, b2 = 0.f, c = 0.f;
#pragma unroll
        for (int i = 0; i < 16; ++i) { a += S->sh[0][i]; b2 += S->sh[1][i]; c += S->sh[2][i]; }
        atomicAdd(&g_acc[1 + 3 * pair], (double)a);
        atomicAdd(&g_acc[2 + 3 * pair], (double)b2);
        atomicAdd(&g_acc[3 + 3 * pair], (double)c);
    }
}

__device__ void do_reg(SmemLcc* S, int b,
    const float4* __restrict__ A, const float4* __restrict__ B)
{
    const int n4 = NF / 4;
    float s = 0.f;
    for (int i = b * 512 + threadIdx.x; i < n4; i += N_REG * 512) {
        float4 a = A[i], bb = B[i];
        float d0 = a.x - bb.x, d1 = a.y - bb.y, d2 = a.z - bb.z, d3 = a.w - bb.w;
        s += d0 * d0 + d1 * d1 + d2 * d2 + d3 * d3;
    }
    int tid = threadIdx.x;
    unsigned lane = tid & 31, wd = tid >> 5;
#pragma unroll
    for (int o = 16; o; o >>= 1) s += __shfl_down_sync(0xffffffffu, s, o);
    if (lane == 0) S->sh[0][wd] = s;
    __syncthreads();
    if (tid == 0) {
        float a = 0.f;
#pragma unroll
        for (int i = 0; i < 16; ++i) a += S->sh[0][i];
        atomicAdd(&g_acc[0], (double)a);
    }
}

__device__ void do_tv(SmemLcc* S, int b,
    const float4* __restrict__ S0, const float4* __restrict__ S0g,
    const float4* __restrict__ S1, const float4* __restrict__ S1g)
{
    const int n4 = NV / 4;
    int p = b >= 512;
    const float4* Sv  = p ? S1  : S0;
    const float4* Sg  = p ? S1g : S0g;
    int bid = b - (p << 9);

    float sp = 0.f, sa = 0.f;
    for (int i = bid * 512 + threadIdx.x; i < n4; i += 512 * 512) {
        float4 a = Sv[i], bb = Sg[i];
        sp += a.x * bb.x + a.y * bb.y + a.z * bb.z + a.w * bb.w;
        sa += a.x + bb.x + a.y + bb.y + a.z + bb.z + a.w + bb.w;
    }
    int tid = threadIdx.x;
    unsigned lane = tid & 31, wd = tid >> 5;
#pragma unroll
    for (int o = 16; o; o >>= 1) {
        sp += __shfl_down_sync(0xffffffffu, sp, o);
        sa += __shfl_down_sync(0xffffffffu, sa, o);
    }
    if (lane == 0) { S->sh[0][wd] = sp; S->sh[1][wd] = sa; }
    __syncthreads();
    if (tid == 0) {
        float a = 0.f, b2 = 0.f;
#pragma unroll
        for (int i = 0; i < 16; ++i) { a += S->sh[0][i]; b2 += S->sh[1][i]; }
        atomicAdd(&g_acc[7 + 2 * p], (double)a);
        atomicAdd(&g_acc[8 + 2 * p], (double)b2);
    }
}

// ---------------------------------------------------------------------------
// Mega kernel, lcc blocks FIRST (dense lcc phase, BW blocks drain the tail).
// Last block to finish finalizes in fp32 (parallel g_acc loads) — no second
// kernel launch, minimal register footprint.
// ---------------------------------------------------------------------------
__global__ void __launch_bounds__(512) k_mega(
    const float* __restrict__ F0,  const float* __restrict__ F0g,
    const float* __restrict__ I0,  const float* __restrict__ I0R,
    const float* __restrict__ I1,  const float* __restrict__ I1R,
    const float* __restrict__ S0,  const float* __restrict__ S0g,
    const float* __restrict__ S1,  const float* __restrict__ S1g,
    float* __restrict__ out)
{
    __shared__ SmemLcc S;
    int b = blockIdx.x;
    int tid = threadIdx.x;
    if (b < N_LCC) {
        do_lcc(&S, b, I0, I0R, I1, I1R);
    } else if (b < N_LCC + N_REG) {
        do_reg(&S, b - N_LCC, (const float4*)F0, (const float4*)F0g);
    } else {
        do_tv(&S, b - N_LCC - N_REG, (const float4*)S0, (const float4*)S0g,
              (const float4*)S1, (const float4*)S1g);
    }

    // completion counter + in-kernel fp32 finalize
    __syncthreads();
    if (tid == 0) {
        __threadfence();                       // release this block's atomics
        unsigned old = atomicAdd(&g_done, 1u);
        S.last = (old == GRID - 1) ? 1u : 0u;
    }
    __syncthreads();
    if (S.last) {
        if (tid < 16) {
            double v = *((volatile double*)&g_acc[tid]);   // all visible via L2
            S.facc[tid] = (float)v;
            g_acc[tid] = 0.0;                  // restore invariant
        }
        __syncthreads();
        if (tid == 0) {
            float reg = sqrtf(S.facc[0]) * (1.0f / (float)NF);
            float l = 0.f;
#pragma unroll
            for (int p = 0; p < 2; ++p) {
                float gp = S.facc[1 + 3 * p], gg = S.facc[2 + 3 * p], pp = S.facc[3 + 3 * p];
                float den = gg * pp;
                if (den < 1e-5f) den = 1e-5f;
                l += -(gp * gp / den) * (1.0f / (float)NV);
            }
            float t = 0.f;
#pragma unroll
            for (int p = 0; p < 2; ++p) {
                float den = S.facc[8 + 2 * p];
                if (den < 1e-5f) den = 1e-5f;
                t += -S.facc[7 + 2 * p] / den;
            }
            out[0] = reg + 10.0f * l + 10.0f * t;
            g_done = 0u;
            __threadfence();
        }
    }
}

extern "C" void kernel_launch(void* const* d_in, const int* in_sizes, int n_in,
                              void* d_out, int out_size) {
    const float* F0  = (const float*)d_in[0];
    const float* F0g = (const float*)d_in[1];
    const float* I0  = (const float*)d_in[2];
    const float* I0R = (const float*)d_in[3];
    const float* I1  = (const float*)d_in[4];
    const float* I1R = (const float*)d_in[5];
    const float* S0  = (const float*)d_in[6];
    const float* S0g = (const float*)d_in[7];
    const float* S1  = (const float*)d_in[8];
    const float* S1g = (const float*)d_in[9];

    k_mega<<<GRID, 512>>>(F0, F0g, I0, I0R, I1, I1R, S0, S0g, S1, S1g,
                          (float*)d_out);
}

// round 15
// speedup vs baseline: 1.0785x; 1.0594x over previous
#include <cuda_runtime.h>
#include <math.h>

#define HW   (128*128)
#define VOL  (128*128*128)
#define NF   12582912
#define NV   4194304

// Accumulators: [0]=reg SSD, [1..3]=pair0 (gp,gg,pp), [4..6]=pair1, [7,8]=tv0(prod,add), [9,10]=tv1
// Zero-initialized at module load; k_final re-zeroes after each use.
__device__ double g_acc[16];

// 16-byte cp.async with zero-fill for out-of-bounds (src-size = 0)
__device__ __forceinline__ void cpa16(void* s, const void* g, bool ok) {
    unsigned sa = (unsigned)__cvta_generic_to_shared(s);
    int sz = ok ? 16 : 0;
    asm volatile("cp.async.cg.shared.global [%0], [%1], 16, %2;\n"
                 :: "r"(sa), "l"(g), "r"(sz) : "memory");
}
__device__ __forceinline__ void cpa_commit() {
    asm volatile("cp.async.commit_group;\n" ::: "memory");
}
__device__ __forceinline__ void cpa_wait1() {
    asm volatile("cp.async.wait_group 1;\n" ::: "memory");
}

#define N_LCC 512
#define N_REG 768
#define N_TV  1024    // 512 per pair
#define GRID  (N_LCC + N_REG + N_TV)

struct __align__(16) SmemLcc {
    float raw[2][2][20][72];   // [buf][vol][row][col]; col 0 = global w0-4
    float xs[2][20][64];       // x-passed 5-sums
    float sh[3][16];
};

// Load one z-plane (both vols, 20 rows x 72 cols) via 16B cp.async.
// Window covers global w0-4 .. w0+67; fully-OOB/pad 4-float groups zero-fill.
__device__ __forceinline__ void load_plane(
    float (*rawbuf)[20][72], const float* __restrict__ gt,
    const float* __restrict__ pr, int z, int h0, int w0, int tid)
{
    bool zv = ((unsigned)z < 128u);
#pragma unroll
    for (int k = 0; k < 2; ++k) {
        int idx = tid + k * 512;
        if (idx < 720) {                       // 2 vols * 20 rows * 18 groups
            int v   = (idx >= 360);
            int rem = idx - (v ? 360 : 0);
            int rr  = rem / 18;
            int g4  = rem - rr * 18;
            int h   = h0 - 2 + rr;
            int gw  = w0 - 4 + g4 * 4;
            bool ok = zv && ((unsigned)h < 128u) && ((unsigned)gw < 128u);
            const float* g = (v ? pr : gt) + (ok ? (z * HW + h * 128 + gw) : 0);
            cpa16(&rawbuf[v][rr][g4 * 4], g, ok);
        }
    }
}

__device__ void do_lcc(SmemLcc* S, int b,
    const float* __restrict__ I0, const float* __restrict__ I0R,
    const float* __restrict__ I1, const float* __restrict__ I1R)
{
    int zs   = b & 7;
    int wt   = (b >> 3) & 1;
    int ht   = (b >> 4) & 7;
    int n    = (b >> 7) & 1;
    int pair = (b >> 8) & 1;

    const float* gt = (pair ? I1  : I0)  + n * VOL;
    const float* pr = (pair ? I1R : I0R) + n * VOL;

    int h0 = ht << 4;
    int w0 = wt << 6;
    int d0 = zs << 4;   // 16-plane z segment

    int tid  = threadIdx.x;
    int wloc = tid & 63;
    int r0   = tid >> 6;         // owns output rows 2r0 and 2r0+1

    float m[2][2][5];            // [rowpair][vol][zwin] xy-sums
    float rc[2][2][3];           // raw-center delay line
#pragma unroll
    for (int c = 0; c < 2; ++c)
#pragma unroll
        for (int v = 0; v < 2; ++v) {
#pragma unroll
            for (int k = 0; k < 5; ++k) m[c][v][k] = 0.f;
#pragma unroll
            for (int k = 0; k < 3; ++k) rc[c][v][k] = 0.f;
        }

    float sgp = 0.f, sgg = 0.f, spp = 0.f;

    load_plane(S->raw[(d0 - 2) & 1], gt, pr, d0 - 2, h0, w0, tid);
    cpa_commit();

    int zlast = d0 + 17;
    for (int z = d0 - 2; z <= zlast; ++z) {
        int buf = z & 1;
        if (z < zlast)
            load_plane(S->raw[(z + 1) & 1], gt, pr, z + 1, h0, w0, tid);
        cpa_commit();
        cpa_wait1();
        __syncthreads();

        // raw-center delay push
#pragma unroll
        for (int c = 0; c < 2; ++c) {
#pragma unroll
            for (int v = 0; v < 2; ++v) {
                rc[c][v][2] = rc[c][v][1];
                rc[c][v][1] = rc[c][v][0];
                rc[c][v][0] = S->raw[buf][v][2 * r0 + c + 2][wloc + 4];
            }
        }

        // x-pass: 320 tasks; each produces 8 adjacent sums from 4 LDS.128
        if (tid < 320) {
            int v   = (tid >= 160);
            int rem = tid - (v ? 160 : 0);
            int rr  = rem >> 3;
            int g   = rem & 7;                 // 8 outputs starting at 8g
            const float4* r4 = (const float4*)S->raw[buf][v][rr];
            float4 A = r4[2 * g], B = r4[2 * g + 1], C = r4[2 * g + 2], D = r4[2 * g + 3];
            float f2 = A.z, f3 = A.w, f4 = B.x, f5 = B.y, f6 = B.z, f7 = B.w;
            float f8 = C.x, f9 = C.y, f10 = C.z, f11 = C.w, f12 = D.x, f13 = D.y;
            float o0 = f2 + f3 + f4 + f5 + f6;
            float o1 = o0 - f2 + f7;
            float o2 = o1 - f3 + f8;
            float o3 = o2 - f4 + f9;
            float o4 = o3 - f5 + f10;
            float o5 = o4 - f6 + f11;
            float o6 = o5 - f7 + f12;
            float o7 = o6 - f8 + f13;
            float4* x4 = (float4*)S->xs[v][rr];
            x4[2 * g]     = make_float4(o0, o1, o2, o3);
            x4[2 * g + 1] = make_float4(o4, o5, o6, o7);
        }
        __syncthreads();

        // y-pass: rows 2r0, 2r0+1 share xs rows 2r0..2r0+5
#pragma unroll
        for (int v = 0; v < 2; ++v) {
            int rl = 2 * r0;
            float y0 = S->xs[v][rl][wloc];
            float y1 = S->xs[v][rl + 1][wloc];
            float y2 = S->xs[v][rl + 2][wloc];
            float y3 = S->xs[v][rl + 3][wloc];
            float y4 = S->xs[v][rl + 4][wloc];
            float y5 = S->xs[v][rl + 5][wloc];
            float mv0 = y0 + y1 + y2 + y3 + y4;
            float mv1 = mv0 - y0 + y5;
            m[0][v][0] = m[0][v][1]; m[0][v][1] = m[0][v][2];
            m[0][v][2] = m[0][v][3]; m[0][v][3] = m[0][v][4]; m[0][v][4] = mv0;
            m[1][v][0] = m[1][v][1]; m[1][v][1] = m[1][v][2];
            m[1][v][2] = m[1][v][3]; m[1][v][3] = m[1][v][4]; m[1][v][4] = mv1;
        }

        if (z >= d0 + 2) {
#pragma unroll
            for (int c = 0; c < 2; ++c) {
                float mg = (m[c][0][0] + m[c][0][1] + m[c][0][2] + m[c][0][3] + m[c][0][4]) * 0.008f;
                float mp = (m[c][1][0] + m[c][1][1] + m[c][1][2] + m[c][1][3] + m[c][1][4]) * 0.008f;
                float dg = rc[c][0][2] - mg;
                float dp = rc[c][1][2] - mp;
                sgp += dg * dp;
                sgg += dg * dg;
                spp += dp * dp;
            }
        }
    }

    unsigned lane = tid & 31, wd = tid >> 5;
#pragma unroll
    for (int o = 16; o; o >>= 1) {
        sgp += __shfl_down_sync(0xffffffffu, sgp, o);
        sgg += __shfl_down_sync(0xffffffffu, sgg, o);
        spp += __shfl_down_sync(0xffffffffu, spp, o);
    }
    if (lane == 0) { S->sh[0][wd] = sgp; S->sh[1][wd] = sgg; S->sh[2][wd] = spp; }
    __syncthreads();
    if (tid == 0) {
        float a = 0.f, b2 = 0.f, c = 0.f;
#pragma unroll
        for (int i = 0; i < 16; ++i) { a += S->sh[0][i]; b2 += S->sh[1][i]; c += S->sh[2][i]; }
        atomicAdd(&g_acc[1 + 3 * pair], (double)a);
        atomicAdd(&g_acc[2 + 3 * pair], (double)b2);
        atomicAdd(&g_acc[3 + 3 * pair], (double)c);
    }
}

__device__ void do_reg(SmemLcc* S, int b,
    const float4* __restrict__ A, const float4* __restrict__ B)
{
    const int n4 = NF / 4;
    float s = 0.f;
    for (int i = b * 512 + threadIdx.x; i < n4; i += N_REG * 512) {
        float4 a = A[i], bb = B[i];
        float d0 = a.x - bb.x, d1 = a.y - bb.y, d2 = a.z - bb.z, d3 = a.w - bb.w;
        s += d0 * d0 + d1 * d1 + d2 * d2 + d3 * d3;
    }
    int tid = threadIdx.x;
    unsigned lane = tid & 31, wd = tid >> 5;
#pragma unroll
    for (int o = 16; o; o >>= 1) s += __shfl_down_sync(0xffffffffu, s, o);
    if (lane == 0) S->sh[0][wd] = s;
    __syncthreads();
    if (tid == 0) {
        float a = 0.f;
#pragma unroll
        for (int i = 0; i < 16; ++i) a += S->sh[0][i];
        atomicAdd(&g_acc[0], (double)a);
    }
}

__device__ void do_tv(SmemLcc* S, int b,
    const float4* __restrict__ S0, const float4* __restrict__ S0g,
    const float4* __restrict__ S1, const float4* __restrict__ S1g)
{
    const int n4 = NV / 4;
    int p = b >= 512;
    const float4* Sv  = p ? S1  : S0;
    const float4* Sg  = p ? S1g : S0g;
    int bid = b - (p << 9);

    float sp = 0.f, sa = 0.f;
    for (int i = bid * 512 + threadIdx.x; i < n4; i += 512 * 512) {
        float4 a = Sv[i], bb = Sg[i];
        sp += a.x * bb.x + a.y * bb.y + a.z * bb.z + a.w * bb.w;
        sa += a.x + bb.x + a.y + bb.y + a.z + bb.z + a.w + bb.w;
    }
    int tid = threadIdx.x;
    unsigned lane = tid & 31, wd = tid >> 5;
#pragma unroll
    for (int o = 16; o; o >>= 1) {
        sp += __shfl_down_sync(0xffffffffu, sp, o);
        sa += __shfl_down_sync(0xffffffffu, sa, o);
    }
    if (lane == 0) { S->sh[0][wd] = sp; S->sh[1][wd] = sa; }
    __syncthreads();
    if (tid == 0) {
        float a = 0.f, b2 = 0.f;
#pragma unroll
        for (int i = 0; i < 16; ++i) { a += S->sh[0][i]; b2 += S->sh[1][i]; }
        atomicAdd(&g_acc[7 + 2 * p], (double)a);
        atomicAdd(&g_acc[8 + 2 * p], (double)b2);
    }
}

// ---------------------------------------------------------------------------
// Mega kernel: lcc blocks first (latency/smem heavy, low DRAM BW), then reg/tv
// blocks (pure BW) backfill and soak up the idle DRAM bandwidth in the tail.
// (Identical to the 73.8us best — no in-kernel finalize tail.)
// ---------------------------------------------------------------------------
__global__ void __launch_bounds__(512) k_mega(
    const float* __restrict__ F0,  const float* __restrict__ F0g,
    const float* __restrict__ I0,  const float* __restrict__ I0R,
    const float* __restrict__ I1,  const float* __restrict__ I1R,
    const float* __restrict__ S0,  const float* __restrict__ S0g,
    const float* __restrict__ S1,  const float* __restrict__ S1g)
{
    __shared__ SmemLcc S;
    int b = blockIdx.x;
    if (b < N_LCC) {
        do_lcc(&S, b, I0, I0R, I1, I1R);
    } else if (b < N_LCC + N_REG) {
        do_reg(&S, b - N_LCC, (const float4*)F0, (const float4*)F0g);
    } else {
        do_tv(&S, b - N_LCC - N_REG, (const float4*)S0, (const float4*)S0g,
              (const float4*)S1, (const float4*)S1g);
    }
}

// Finalize, launched with PDL: pre-launched during k_mega, waits on the grid
// dependency, then runs immediately — hides the small-kernel launch overhead.
__global__ void k_final(float* out) {
#if __CUDA_ARCH__ >= 900
    cudaGridDependencySynchronize();
#endif
    __shared__ double a[16];
    int t = threadIdx.x;
    if (t < 16) a[t] = g_acc[t];
    __syncwarp();
    if (t == 0) {
        double reg = sqrt(a[0]) / (double)NF;
        double l = 0.0;
        for (int p = 0; p < 2; ++p) {
            double gp = a[1 + 3 * p], gg = a[2 + 3 * p], pp = a[3 + 3 * p];
            double den = gg * pp;
            if (den < 1e-5) den = 1e-5;
            l += -(gp * gp / den) / (double)NV;
        }
        double tv = 0.0;
        for (int p = 0; p < 2; ++p) {
            double den = a[8 + 2 * p];
            if (den < 1e-5) den = 1e-5;
            tv += -a[7 + 2 * p] / den;
        }
        out[0] = (float)(reg + 10.0 * l + 10.0 * tv);
    }
    __syncwarp();
    if (t < 16) g_acc[t] = 0.0;   // restore invariant for next replay
}

extern "C" void kernel_launch(void* const* d_in, const int* in_sizes, int n_in,
                              void* d_out, int out_size) {
    const float* F0  = (const float*)d_in[0];
    const float* F0g = (const float*)d_in[1];
    const float* I0  = (const float*)d_in[2];
    const float* I0R = (const float*)d_in[3];
    const float* I1  = (const float*)d_in[4];
    const float* I1R = (const float*)d_in[5];
    const float* S0  = (const float*)d_in[6];
    const float* S0g = (const float*)d_in[7];
    const float* S1  = (const float*)d_in[8];
    const float* S1g = (const float*)d_in[9];

    k_mega<<<GRID, 512>>>(F0, F0g, I0, I0R, I1, I1R, S0, S0g, S1, S1g);

    // PDL launch of k_final: overlaps its launch latency with k_mega.
    cudaLaunchConfig_t cfg = {};
    cfg.gridDim  = dim3(1, 1, 1);
    cfg.blockDim = dim3(32, 1, 1);
    cudaLaunchAttribute attr[1];
    attr[0].id = cudaLaunchAttributeProgrammaticStreamSerialization;
    attr[0].val.programmaticStreamSerializationAllowed = 1;
    cfg.attrs = attr;
    cfg.numAttrs = 1;
    cudaError_t e = cudaLaunchKernelEx(&cfg, k_final, (float*)d_out);
    if (e != cudaSuccess) {
        // fallback: plain launch (still correct, just pays launch latency)
        k_final<<<1, 32>>>((float*)d_out);
    }
}